// round 11
// baseline (speedup 1.0000x reference)
#include <cuda_runtime.h>
#include <cuda_bf16.h>
#include <stdint.h>
#include <math.h>

#define L_SEQ 4096
#define BATCH 2
#define HID   1024
#define DHEAD 64
#define CHUNK 64
#define NCHUNK (L_SEQ / CHUNK)
#define ROWS  (BATCH * L_SEQ)
#define GAMMA_F 0.96875f
#define LOG2_GAMMA (-0.04580368961f)
#define SDEPTH 16   // gamma^(64*16) ~ 7e-15: below fp32 noise

// Scratch (__device__ globals; no allocations allowed)
__device__ __nv_bfloat16 g_Xh[ROWS * HID];
__device__ __nv_bfloat16 g_Xl[ROWS * HID];
__device__ __nv_bfloat16 g_Wth[3 * DHEAD * HID];   // [which][n][k]
__device__ __nv_bfloat16 g_Wtl[3 * DHEAD * HID];
__device__ float g_Q[ROWS * DHEAD];
__device__ float g_K[ROWS * DHEAD];
__device__ float g_V[ROWS * DHEAD];
__device__ float g_A[BATCH * NCHUNK * DHEAD * DHEAD];

#define MMA16816(d, a, b)                                                   \
    asm volatile(                                                           \
        "mma.sync.aligned.m16n8k16.row.col.f32.bf16.bf16.f32 "              \
        "{%0,%1,%2,%3}, {%4,%5,%6,%7}, {%8,%9}, {%0,%1,%2,%3};\n"           \
        : "+f"(d[0]), "+f"(d[1]), "+f"(d[2]), "+f"(d[3])                    \
        : "r"(a[0]), "r"(a[1]), "r"(a[2]), "r"(a[3]), "r"(b[0]), "r"(b[1]))

// ---------------------------------------------------------------------------
// P0: split X (fp32 -> bf16 hi/lo) and transpose+split W, one launch.
// ---------------------------------------------------------------------------
__global__ __launch_bounds__(256) void split_kernel(
    const float* __restrict__ X,
    const float* __restrict__ WQ,
    const float* __restrict__ WK,
    const float* __restrict__ WV) {
    if (blockIdx.x < 4096) {
        const size_t tid = (size_t)blockIdx.x * 256 + threadIdx.x;
        const float4* p = (const float4*)X + tid * 2;
        float4 a = p[0], b = p[1];
        float v[8] = {a.x, a.y, a.z, a.w, b.x, b.y, b.z, b.w};
        __nv_bfloat162 hh[4], ll[4];
#pragma unroll
        for (int i = 0; i < 4; i++) {
            __nv_bfloat16 h0 = __float2bfloat16(v[2 * i + 0]);
            __nv_bfloat16 h1 = __float2bfloat16(v[2 * i + 1]);
            hh[i] = __nv_bfloat162(h0, h1);
            ll[i] = __nv_bfloat162(__float2bfloat16(v[2 * i + 0] - __bfloat162float(h0)),
                                   __float2bfloat16(v[2 * i + 1] - __bfloat162float(h1)));
        }
        *(uint4*)&g_Xh[tid * 8] = *(uint4*)hh;
        *(uint4*)&g_Xl[tid * 8] = *(uint4*)ll;
    } else {
        int idx = (blockIdx.x - 4096) * 256 + threadIdx.x;
#pragma unroll
        for (int e = 0; e < 4; e++, idx += 49152) {
            const int which = idx >> 16;
            const int rem   = idx & 65535;
            const int n = rem >> 10, k = rem & 1023;
            const float* W = (which == 0) ? WQ : ((which == 1) ? WK : WV);
            const float v = W[(size_t)k * DHEAD + n];
            __nv_bfloat16 h = __float2bfloat16(v);
            g_Wth[idx] = h;
            g_Wtl[idx] = __float2bfloat16(v - __bfloat162float(h));
        }
    }
}

// ---------------------------------------------------------------------------
// P1: projection (unchanged from R9 — near mma.sync roofline).
// ---------------------------------------------------------------------------
__global__ __launch_bounds__(256) void proj_mma_kernel() {
    const int which = blockIdx.y;
    float* __restrict__ Out = (which == 0) ? g_Q : ((which == 1) ? g_K : g_V);
    const __nv_bfloat16* __restrict__ Wh = g_Wth + (size_t)which * DHEAD * HID;
    const __nv_bfloat16* __restrict__ Wl = g_Wtl + (size_t)which * DHEAD * HID;

    __shared__ __nv_bfloat16 Ah[64][72];
    __shared__ __nv_bfloat16 Al[64][72];
    __shared__ __nv_bfloat16 Bh[64][72];
    __shared__ __nv_bfloat16 Bl[64][72];

    const int t    = threadIdx.x;
    const int warp = t >> 5, lane = t & 31;
    const int grp  = lane >> 2, tig = lane & 3;
    const int wm   = warp >> 1;
    const int wn   = warp & 1;
    const int m0   = blockIdx.x * 64;

    const int r0 = t >> 3, c8 = (t & 7) * 8;

    uint4 rXh[2], rXl[2], rWh[2], rWl[2];

    auto issue = [&](int k0) {
#pragma unroll
        for (int e = 0; e < 2; e++) {
            const int row = r0 + e * 32;
            const size_t xo = (size_t)(m0 + row) * HID + k0 + c8;
            rXh[e] = *(const uint4*)(g_Xh + xo);
            rXl[e] = *(const uint4*)(g_Xl + xo);
            const size_t wo = (size_t)row * HID + k0 + c8;
            rWh[e] = *(const uint4*)(Wh + wo);
            rWl[e] = *(const uint4*)(Wl + wo);
        }
    };

    float acc[4][4];
#pragma unroll
    for (int nt = 0; nt < 4; nt++)
#pragma unroll
        for (int c = 0; c < 4; c++) acc[nt][c] = 0.0f;

    issue(0);
    for (int k0 = 0; k0 < HID; k0 += 64) {
#pragma unroll
        for (int e = 0; e < 2; e++) {
            const int row = r0 + e * 32;
            *(uint4*)&Ah[row][c8] = rXh[e];
            *(uint4*)&Al[row][c8] = rXl[e];
            *(uint4*)&Bh[row][c8] = rWh[e];
            *(uint4*)&Bl[row][c8] = rWl[e];
        }
        __syncthreads();
        if (k0 + 64 < HID) issue(k0 + 64);

#pragma unroll
        for (int ks = 0; ks < 64; ks += 16) {
            const int r = wm * 16 + grp;
            const int c = ks + tig * 2;
            uint32_t ah[4], al[4];
            ah[0] = *(const uint32_t*)&Ah[r][c];
            ah[1] = *(const uint32_t*)&Ah[r + 8][c];
            ah[2] = *(const uint32_t*)&Ah[r][c + 8];
            ah[3] = *(const uint32_t*)&Ah[r + 8][c + 8];
            al[0] = *(const uint32_t*)&Al[r][c];
            al[1] = *(const uint32_t*)&Al[r + 8][c];
            al[2] = *(const uint32_t*)&Al[r][c + 8];
            al[3] = *(const uint32_t*)&Al[r + 8][c + 8];
#pragma unroll
            for (int nt = 0; nt < 4; nt++) {
                const int n = wn * 32 + nt * 8 + grp;
                uint32_t bh[2], bl[2];
                bh[0] = *(const uint32_t*)&Bh[n][c];
                bh[1] = *(const uint32_t*)&Bh[n][c + 8];
                bl[0] = *(const uint32_t*)&Bl[n][c];
                bl[1] = *(const uint32_t*)&Bl[n][c + 8];
                MMA16816(acc[nt], ah, bh);
                MMA16816(acc[nt], ah, bl);
                MMA16816(acc[nt], al, bh);
            }
        }
        __syncthreads();
    }

    const bool dox  = (which < 2);
    const bool down = (which == 1);
#pragma unroll
    for (int nt = 0; nt < 4; nt++) {
        const int col = wn * 32 + nt * 8 + tig * 2;
        const int h   = col >> 1;
        float lsv = 0.f, invf = 0.f;
        if (dox) {
            lsv  = __log2f(((float)col + 25.6f) / 89.6f);
            invf = exp2f((float)h * (-13.287712379549449f / 32.0f));
        }
#pragma unroll
        for (int half = 0; half < 2; half++) {
            const int rr = m0 + wm * 16 + grp + half * 8;
            float x0 = acc[nt][half * 2 + 0];
            float x1 = acc[nt][half * 2 + 1];
            if (dox) {
                const float pos = (float)(rr & (L_SEQ - 1));
                float e = lsv * pos * (1.0f / 512.0f);
                if (down) e = -e;
                const float sc = exp2f(e);
                float s, cg;
                sincosf(pos * invf, &s, &cg);
                s *= sc; cg *= sc;
                const float y0 = x0 * cg - x1 * s;
                const float y1 = x1 * cg + x0 * s;
                x0 = y0; x1 = y1;
            }
            *(float2*)(Out + (size_t)rr * DHEAD + col) = make_float2(x0, x1);
        }
    }
}

// ---------------------------------------------------------------------------
// P2: per-chunk decayed A_j = (decayed K)^T V, z-split over 4 column quarters.
// ---------------------------------------------------------------------------
__global__ __launch_bounds__(256) void chunk_stats_kernel() {
    const int j  = blockIdx.x;
    const int b  = blockIdx.y;
    const int cb = blockIdx.z * 16;
    __shared__ float Ks[CHUNK][DHEAD];
    __shared__ float Vs[CHUNK][17];

    const int t = threadIdx.x;
    const size_t base = (size_t)(b * L_SEQ + j * CHUNK) * DHEAD;
    for (int i = t; i < CHUNK * DHEAD; i += 256) {
        const int r = i >> 6, d = i & 63;
        const float w = exp2f((float)(CHUNK - 1 - r) * LOG2_GAMMA);
        Ks[r][d] = g_K[base + i] * w;
    }
    for (int i = t; i < CHUNK * 16; i += 256) {
        const int r = i >> 4, d = i & 15;
        Vs[r][d] = g_V[base + r * DHEAD + cb + d];
    }
    __syncthreads();

    const int ty = t >> 4, tx = t & 15;    // 4 rows x 1 col per thread
    float acc[4] = {0.f, 0.f, 0.f, 0.f};

    for (int r = 0; r < CHUNK; r++) {
        const float v = Vs[r][tx];
#pragma unroll
        for (int i = 0; i < 4; i++)
            acc[i] = fmaf(Ks[r][ty * 4 + i], v, acc[i]);
    }

    float* __restrict__ Ap = g_A + (size_t)(b * NCHUNK + j) * DHEAD * DHEAD;
#pragma unroll
    for (int i = 0; i < 4; i++)
        Ap[(ty * 4 + i) * DHEAD + cb + tx] = acc[i];
}

// ---------------------------------------------------------------------------
// P3: per-chunk output, 4-way split (rowhalf x colhalf), 256 threads.
// O[r] = sum_{r'<=r} g^(r-r') (q_r.k_r') v_r'  +  g^(r+1) q_r . S_j
// ---------------------------------------------------------------------------
__global__ __launch_bounds__(256) void out_kernel(float* __restrict__ O) {
    const int j  = blockIdx.x;
    const int b  = blockIdx.y;
    const int rb = (blockIdx.z >> 1) * 32;   // row base within chunk
    const int cb = (blockIdx.z & 1) * 32;    // col base

    __shared__ float Qs[32][67];     // Q rows rb..rb+31 (col-accessed: odd-ish pad)
    __shared__ float Kt[64][66];     // K transposed [d][r], full chunk
    __shared__ float Ps[32][67];     // masked P rows, all 64 rp
    __shared__ float VS[128][36];    // rows 0..63: V slice | 64..127: S slice
    __shared__ float gpow[CHUNK + 1];

    const int t = threadIdx.x;
    const size_t base = (size_t)(b * L_SEQ + j * CHUNK) * DHEAD;

    for (int i = t; i < 32 * DHEAD; i += 256) {
        const int r = i >> 6, d = i & 63;
        Qs[r][d] = g_Q[base + (rb + r) * DHEAD + d];
    }
    for (int i = t; i < CHUNK * DHEAD; i += 256) {
        const int r = i >> 6, d = i & 63;
        Kt[d][r] = g_K[base + i];
    }
    for (int i = t; i < CHUNK * 32; i += 256) {
        const int r = i >> 5, d = i & 31;
        VS[r][d] = g_V[base + r * DHEAD + cb + d];
    }
    if (t <= CHUNK) gpow[t] = exp2f((float)t * LOG2_GAMMA);

    // Windowed state slice S_j (gmem -> regs), 8 floats/thread
    float s8[8] = {0.f, 0.f, 0.f, 0.f, 0.f, 0.f, 0.f, 0.f};
    {
        const int sr = t >> 2;            // 0..63
        const int sc = (t & 3) * 8;       // 0,8,16,24
        const int dmax = (j < SDEPTH) ? j : SDEPTH;
        const float gC = exp2f((float)CHUNK * LOG2_GAMMA);
        float w = 1.0f;
        for (int d = 1; d <= dmax; d++) {
            const float* Ap = g_A + (size_t)(b * NCHUNK + j - d) * 4096;
            float4 u0 = *(const float4*)(Ap + sr * DHEAD + cb + sc);
            float4 u1 = *(const float4*)(Ap + sr * DHEAD + cb + sc + 4);
            s8[0] += w * u0.x; s8[1] += w * u0.y; s8[2] += w * u0.z; s8[3] += w * u0.w;
            s8[4] += w * u1.x; s8[5] += w * u1.y; s8[6] += w * u1.z; s8[7] += w * u1.w;
            w *= gC;
        }
    }
    __syncthreads();   // Qs/Kt/V/gpow ready

    // Park S slice into VS[64..127] (read only after next sync)
    {
        const int sr = t >> 2;
        const int sc = (t & 3) * 8;
#pragma unroll
        for (int e = 0; e < 8; e++) VS[64 + sr][sc + e] = s8[e];
    }

    // Phase 1: P[32 x 64] = Q K^T with decay mask. 4 rows x 2 cols per thread.
    {
        const int ty = t >> 5, tx = t & 31;
        float p[4][2];
#pragma unroll
        for (int i = 0; i < 4; i++) { p[i][0] = 0.f; p[i][1] = 0.f; }
        for (int d = 0; d < DHEAD; d++) {
            float q[4];
#pragma unroll
            for (int i = 0; i < 4; i++) q[i] = Qs[ty * 4 + i][d];
            const float2 k2 = *(const float2*)&Kt[d][tx * 2];
#pragma unroll
            for (int i = 0; i < 4; i++) {
                p[i][0] = fmaf(q[i], k2.x, p[i][0]);
                p[i][1] = fmaf(q[i], k2.y, p[i][1]);
            }
        }
#pragma unroll
        for (int i = 0; i < 4; i++) {
            const int rg = rb + ty * 4 + i;          // global row in chunk
#pragma unroll
            for (int jj = 0; jj < 2; jj++) {
                const int rp = tx * 2 + jj;
                Ps[ty * 4 + i][rp] = (rg >= rp) ? p[i][jj] * gpow[rg - rp] : 0.0f;
            }
        }
    }
    __syncthreads();   // Ps + VS(S) ready

    // Phase 2+3 back-to-back (no intermediate sync): O = P@V + g^(r+1) Q@S
    const int ty2 = t >> 4, tx2 = t & 15;     // 2 rows x 2 cols per thread
    float o[2][2] = {{0.f, 0.f}, {0.f, 0.f}};
    float cc[2][2] = {{0.f, 0.f}, {0.f, 0.f}};
    for (int r2 = 0; r2 < CHUNK; r2++) {
        const float p0 = Ps[ty2 * 2 + 0][r2];
        const float p1 = Ps[ty2 * 2 + 1][r2];
        const float2 v2 = *(const float2*)&VS[r2][tx2 * 2];
        o[0][0] = fmaf(p0, v2.x, o[0][0]);
        o[0][1] = fmaf(p0, v2.y, o[0][1]);
        o[1][0] = fmaf(p1, v2.x, o[1][0]);
        o[1][1] = fmaf(p1, v2.y, o[1][1]);
        const float q0 = Qs[ty2 * 2 + 0][r2];
        const float q1 = Qs[ty2 * 2 + 1][r2];
        const float2 s2 = *(const float2*)&VS[64 + r2][tx2 * 2];
        cc[0][0] = fmaf(q0, s2.x, cc[0][0]);
        cc[0][1] = fmaf(q0, s2.y, cc[0][1]);
        cc[1][0] = fmaf(q1, s2.x, cc[1][0]);
        cc[1][1] = fmaf(q1, s2.y, cc[1][1]);
    }

#pragma unroll
    for (int i = 0; i < 2; i++) {
        const int rg = rb + ty2 * 2 + i;
        const float g = gpow[rg + 1];
        const size_t orow = (size_t)(b * L_SEQ + j * CHUNK + rg) * DHEAD;
        O[orow + cb + tx2 * 2 + 0] = o[i][0] + g * cc[i][0];
        O[orow + cb + tx2 * 2 + 1] = o[i][1] + g * cc[i][1];
    }
}

// ---------------------------------------------------------------------------
extern "C" void kernel_launch(void* const* d_in, const int* in_sizes, int n_in,
                              void* d_out, int out_size) {
    const float* X  = (const float*)d_in[0];
    const float* WQ = (const float*)d_in[1];
    const float* WK = (const float*)d_in[2];
    const float* WV = (const float*)d_in[3];
    float* O = (float*)d_out;

    split_kernel<<<4288, 256>>>(X, WQ, WK, WV);
    proj_mma_kernel<<<dim3(ROWS / 64, 3), 256>>>();
    chunk_stats_kernel<<<dim3(NCHUNK, BATCH, 4), 256>>>();
    out_kernel<<<dim3(NCHUNK, BATCH, 4), 256>>>(O);
}

// round 13
// speedup vs baseline: 1.0538x; 1.0538x over previous
#include <cuda_runtime.h>
#include <cuda_bf16.h>
#include <stdint.h>
#include <math.h>

#define L_SEQ 4096
#define BATCH 2
#define HID   1024
#define DHEAD 64
#define CHUNK 64
#define NCHUNK (L_SEQ / CHUNK)
#define ROWS  (BATCH * L_SEQ)
#define GAMMA_F 0.96875f
#define LOG2_GAMMA (-0.04580368961f)
#define SDEPTH 16   // gamma^(64*16) ~ 7e-15: below fp32 noise

// Scratch (__device__ globals; no allocations allowed)
__device__ __nv_bfloat16 g_Xh[ROWS * HID];
__device__ __nv_bfloat16 g_Xl[ROWS * HID];
__device__ __nv_bfloat16 g_Wth[3 * DHEAD * HID];   // [which][n][k]
__device__ __nv_bfloat16 g_Wtl[3 * DHEAD * HID];
__device__ float g_Q[ROWS * DHEAD];
__device__ float g_K[ROWS * DHEAD];
__device__ float g_V[ROWS * DHEAD];
__device__ float g_A[BATCH * NCHUNK * DHEAD * DHEAD];

#define MMA16816(d, a, b)                                                   \
    asm volatile(                                                           \
        "mma.sync.aligned.m16n8k16.row.col.f32.bf16.bf16.f32 "              \
        "{%0,%1,%2,%3}, {%4,%5,%6,%7}, {%8,%9}, {%0,%1,%2,%3};\n"           \
        : "+f"(d[0]), "+f"(d[1]), "+f"(d[2]), "+f"(d[3])                    \
        : "r"(a[0]), "r"(a[1]), "r"(a[2]), "r"(a[3]), "r"(b[0]), "r"(b[1]))

// ---------------------------------------------------------------------------
// P0: split X (fp32 -> bf16 hi/lo) and transpose+split W, one launch.
// ---------------------------------------------------------------------------
__global__ __launch_bounds__(256) void split_kernel(
    const float* __restrict__ X,
    const float* __restrict__ WQ,
    const float* __restrict__ WK,
    const float* __restrict__ WV) {
    if (blockIdx.x < 4096) {
        const size_t tid = (size_t)blockIdx.x * 256 + threadIdx.x;
        const float4* p = (const float4*)X + tid * 2;
        float4 a = p[0], b = p[1];
        float v[8] = {a.x, a.y, a.z, a.w, b.x, b.y, b.z, b.w};
        __nv_bfloat162 hh[4], ll[4];
#pragma unroll
        for (int i = 0; i < 4; i++) {
            __nv_bfloat16 h0 = __float2bfloat16(v[2 * i + 0]);
            __nv_bfloat16 h1 = __float2bfloat16(v[2 * i + 1]);
            hh[i] = __nv_bfloat162(h0, h1);
            ll[i] = __nv_bfloat162(__float2bfloat16(v[2 * i + 0] - __bfloat162float(h0)),
                                   __float2bfloat16(v[2 * i + 1] - __bfloat162float(h1)));
        }
        *(uint4*)&g_Xh[tid * 8] = *(uint4*)hh;
        *(uint4*)&g_Xl[tid * 8] = *(uint4*)ll;
    } else {
        int idx = (blockIdx.x - 4096) * 256 + threadIdx.x;
#pragma unroll
        for (int e = 0; e < 4; e++, idx += 49152) {
            const int which = idx >> 16;
            const int rem   = idx & 65535;
            const int n = rem >> 10, k = rem & 1023;
            const float* W = (which == 0) ? WQ : ((which == 1) ? WK : WV);
            const float v = W[(size_t)k * DHEAD + n];
            __nv_bfloat16 h = __float2bfloat16(v);
            g_Wth[idx] = h;
            g_Wtl[idx] = __float2bfloat16(v - __bfloat162float(h));
        }
    }
}

// ---------------------------------------------------------------------------
// P1: projection (unchanged — near mma.sync roofline).
// ---------------------------------------------------------------------------
__global__ __launch_bounds__(256) void proj_mma_kernel() {
    const int which = blockIdx.y;
    float* __restrict__ Out = (which == 0) ? g_Q : ((which == 1) ? g_K : g_V);
    const __nv_bfloat16* __restrict__ Wh = g_Wth + (size_t)which * DHEAD * HID;
    const __nv_bfloat16* __restrict__ Wl = g_Wtl + (size_t)which * DHEAD * HID;

    __shared__ __nv_bfloat16 Ah[64][72];
    __shared__ __nv_bfloat16 Al[64][72];
    __shared__ __nv_bfloat16 Bh[64][72];
    __shared__ __nv_bfloat16 Bl[64][72];

    const int t    = threadIdx.x;
    const int warp = t >> 5, lane = t & 31;
    const int grp  = lane >> 2, tig = lane & 3;
    const int wm   = warp >> 1;
    const int wn   = warp & 1;
    const int m0   = blockIdx.x * 64;

    const int r0 = t >> 3, c8 = (t & 7) * 8;

    uint4 rXh[2], rXl[2], rWh[2], rWl[2];

    auto issue = [&](int k0) {
#pragma unroll
        for (int e = 0; e < 2; e++) {
            const int row = r0 + e * 32;
            const size_t xo = (size_t)(m0 + row) * HID + k0 + c8;
            rXh[e] = *(const uint4*)(g_Xh + xo);
            rXl[e] = *(const uint4*)(g_Xl + xo);
            const size_t wo = (size_t)row * HID + k0 + c8;
            rWh[e] = *(const uint4*)(Wh + wo);
            rWl[e] = *(const uint4*)(Wl + wo);
        }
    };

    float acc[4][4];
#pragma unroll
    for (int nt = 0; nt < 4; nt++)
#pragma unroll
        for (int c = 0; c < 4; c++) acc[nt][c] = 0.0f;

    issue(0);
    for (int k0 = 0; k0 < HID; k0 += 64) {
#pragma unroll
        for (int e = 0; e < 2; e++) {
            const int row = r0 + e * 32;
            *(uint4*)&Ah[row][c8] = rXh[e];
            *(uint4*)&Al[row][c8] = rXl[e];
            *(uint4*)&Bh[row][c8] = rWh[e];
            *(uint4*)&Bl[row][c8] = rWl[e];
        }
        __syncthreads();
        if (k0 + 64 < HID) issue(k0 + 64);

#pragma unroll
        for (int ks = 0; ks < 64; ks += 16) {
            const int r = wm * 16 + grp;
            const int c = ks + tig * 2;
            uint32_t ah[4], al[4];
            ah[0] = *(const uint32_t*)&Ah[r][c];
            ah[1] = *(const uint32_t*)&Ah[r + 8][c];
            ah[2] = *(const uint32_t*)&Ah[r][c + 8];
            ah[3] = *(const uint32_t*)&Ah[r + 8][c + 8];
            al[0] = *(const uint32_t*)&Al[r][c];
            al[1] = *(const uint32_t*)&Al[r + 8][c];
            al[2] = *(const uint32_t*)&Al[r][c + 8];
            al[3] = *(const uint32_t*)&Al[r + 8][c + 8];
#pragma unroll
            for (int nt = 0; nt < 4; nt++) {
                const int n = wn * 32 + nt * 8 + grp;
                uint32_t bh[2], bl[2];
                bh[0] = *(const uint32_t*)&Bh[n][c];
                bh[1] = *(const uint32_t*)&Bh[n][c + 8];
                bl[0] = *(const uint32_t*)&Bl[n][c];
                bl[1] = *(const uint32_t*)&Bl[n][c + 8];
                MMA16816(acc[nt], ah, bh);
                MMA16816(acc[nt], ah, bl);
                MMA16816(acc[nt], al, bh);
            }
        }
        __syncthreads();
    }

    const bool dox  = (which < 2);
    const bool down = (which == 1);
#pragma unroll
    for (int nt = 0; nt < 4; nt++) {
        const int col = wn * 32 + nt * 8 + tig * 2;
        const int h   = col >> 1;
        float lsv = 0.f, invf = 0.f;
        if (dox) {
            lsv  = __log2f(((float)col + 25.6f) / 89.6f);
            invf = exp2f((float)h * (-13.287712379549449f / 32.0f));
        }
#pragma unroll
        for (int half = 0; half < 2; half++) {
            const int rr = m0 + wm * 16 + grp + half * 8;
            float x0 = acc[nt][half * 2 + 0];
            float x1 = acc[nt][half * 2 + 1];
            if (dox) {
                const float pos = (float)(rr & (L_SEQ - 1));
                float e = lsv * pos * (1.0f / 512.0f);
                if (down) e = -e;
                const float sc = exp2f(e);
                float s, cg;
                sincosf(pos * invf, &s, &cg);
                s *= sc; cg *= sc;
                const float y0 = x0 * cg - x1 * s;
                const float y1 = x1 * cg + x0 * s;
                x0 = y0; x1 = y1;
            }
            *(float2*)(Out + (size_t)rr * DHEAD + col) = make_float2(x0, x1);
        }
    }
}

// ---------------------------------------------------------------------------
// P2: per-chunk decayed A_j = (decayed K)^T V, z-split over 4 column quarters.
// ---------------------------------------------------------------------------
__global__ __launch_bounds__(256) void chunk_stats_kernel() {
    const int j  = blockIdx.x;
    const int b  = blockIdx.y;
    const int cb = blockIdx.z * 16;
    __shared__ float Ks[CHUNK][DHEAD];
    __shared__ float Vs[CHUNK][17];

    const int t = threadIdx.x;
    const size_t base = (size_t)(b * L_SEQ + j * CHUNK) * DHEAD;
    for (int i = t; i < CHUNK * DHEAD; i += 256) {
        const int r = i >> 6, d = i & 63;
        const float w = exp2f((float)(CHUNK - 1 - r) * LOG2_GAMMA);
        Ks[r][d] = g_K[base + i] * w;
    }
    for (int i = t; i < CHUNK * 16; i += 256) {
        const int r = i >> 4, d = i & 15;
        Vs[r][d] = g_V[base + r * DHEAD + cb + d];
    }
    __syncthreads();

    const int ty = t >> 4, tx = t & 15;
    float acc[4] = {0.f, 0.f, 0.f, 0.f};

    for (int r = 0; r < CHUNK; r++) {
        const float v = Vs[r][tx];
#pragma unroll
        for (int i = 0; i < 4; i++)
            acc[i] = fmaf(Ks[r][ty * 4 + i], v, acc[i]);
    }

    float* __restrict__ Ap = g_A + (size_t)(b * NCHUNK + j) * DHEAD * DHEAD;
#pragma unroll
    for (int i = 0; i < 4; i++)
        Ap[(ty * 4 + i) * DHEAD + cb + tx] = acc[i];
}

// ---------------------------------------------------------------------------
// P3: per-chunk output, ROW-split (z=2, 32 rows each), 512 threads.
// Phase-1 P is partitioned (not duplicated).  Phases 2+3 fused.
// float2-accessed arrays use EVEN pitch 66 (+ align 8) — fixes R12 crash.
// ---------------------------------------------------------------------------
__global__ __launch_bounds__(512) void out_kernel(float* __restrict__ O) {
    const int j  = blockIdx.x;
    const int b  = blockIdx.y;
    const int rb = blockIdx.z * 32;          // row base within chunk

    __shared__ float Qs[32][65];                       // scalar access
    __shared__ __align__(8) float Kt[64][66];          // float2 access
    __shared__ float Ps[32][65];                       // scalar access
    __shared__ __align__(8) float Vs[64][66];          // float2 access
    __shared__ __align__(8) float Ss[64][66];          // float2 access
    __shared__ float gpow[CHUNK + 1];

    const int t = threadIdx.x;
    const size_t base = (size_t)(b * L_SEQ + j * CHUNK) * DHEAD;

    for (int i = t; i < 32 * DHEAD; i += 512) {
        const int r = i >> 6, d = i & 63;
        Qs[r][d] = g_Q[base + (rb + r) * DHEAD + d];
    }
    for (int i = t; i < CHUNK * DHEAD; i += 512) {
        const int r = i >> 6, d = i & 63;
        Kt[d][r] = g_K[base + i];
        Vs[r][d] = g_V[base + i];
    }
    if (t <= CHUNK) gpow[t] = exp2f((float)t * LOG2_GAMMA);

    // Windowed state S_j (full 64x64; 8 floats/thread) straight into Ss.
    {
        const int sr = t >> 3;            // 0..63
        const int sc = (t & 7) * 8;       // 0,8,...,56
        float s8[8] = {0.f, 0.f, 0.f, 0.f, 0.f, 0.f, 0.f, 0.f};
        const int dmax = (j < SDEPTH) ? j : SDEPTH;
        const float gC = exp2f((float)CHUNK * LOG2_GAMMA);
        float w = 1.0f;
        for (int d = 1; d <= dmax; d++) {
            const float* Ap = g_A + (size_t)(b * NCHUNK + j - d) * 4096;
            float4 u0 = *(const float4*)(Ap + sr * DHEAD + sc);
            float4 u1 = *(const float4*)(Ap + sr * DHEAD + sc + 4);
            s8[0] += w * u0.x; s8[1] += w * u0.y; s8[2] += w * u0.z; s8[3] += w * u0.w;
            s8[4] += w * u1.x; s8[5] += w * u1.y; s8[6] += w * u1.z; s8[7] += w * u1.w;
            w *= gC;
        }
#pragma unroll
        for (int e = 0; e < 8; e++) Ss[sr][sc + e] = s8[e];
    }
    __syncthreads();   // all smem ready

    // Phase 1: P[32 x 64] = Q K^T * decay-mask.  2 rows x 2 cols per thread.
    {
        const int ty = t >> 5;            // 0..15 -> rows ty*2, ty*2+1
        const int tx = t & 31;            // cols tx*2, tx*2+1
        float p[2][2] = {{0.f, 0.f}, {0.f, 0.f}};
        for (int d = 0; d < DHEAD; d++) {
            const float q0 = Qs[ty * 2 + 0][d];
            const float q1 = Qs[ty * 2 + 1][d];
            const float2 k2 = *(const float2*)&Kt[d][tx * 2];
            p[0][0] = fmaf(q0, k2.x, p[0][0]);
            p[0][1] = fmaf(q0, k2.y, p[0][1]);
            p[1][0] = fmaf(q1, k2.x, p[1][0]);
            p[1][1] = fmaf(q1, k2.y, p[1][1]);
        }
#pragma unroll
        for (int i = 0; i < 2; i++) {
            const int rg = rb + ty * 2 + i;
#pragma unroll
            for (int jj = 0; jj < 2; jj++) {
                const int rp = tx * 2 + jj;
                Ps[ty * 2 + i][rp] = (rg >= rp) ? p[i][jj] * gpow[rg - rp] : 0.0f;
            }
        }
    }
    __syncthreads();

    // Phase 2+3 fused: O = P@V + g^(r+1) * Q@S  (2 rows x 2 cols per thread)
    const int ty2 = t >> 5, tx2 = t & 31;
    float o[2][2] = {{0.f, 0.f}, {0.f, 0.f}};
    float cc[2][2] = {{0.f, 0.f}, {0.f, 0.f}};
    for (int r2 = 0; r2 < CHUNK; r2++) {
        const float p0 = Ps[ty2 * 2 + 0][r2];
        const float p1 = Ps[ty2 * 2 + 1][r2];
        const float2 v2 = *(const float2*)&Vs[r2][tx2 * 2];
        o[0][0] = fmaf(p0, v2.x, o[0][0]);
        o[0][1] = fmaf(p0, v2.y, o[0][1]);
        o[1][0] = fmaf(p1, v2.x, o[1][0]);
        o[1][1] = fmaf(p1, v2.y, o[1][1]);
        const float q0 = Qs[ty2 * 2 + 0][r2];
        const float q1 = Qs[ty2 * 2 + 1][r2];
        const float2 s2 = *(const float2*)&Ss[r2][tx2 * 2];
        cc[0][0] = fmaf(q0, s2.x, cc[0][0]);
        cc[0][1] = fmaf(q0, s2.y, cc[0][1]);
        cc[1][0] = fmaf(q1, s2.x, cc[1][0]);
        cc[1][1] = fmaf(q1, s2.y, cc[1][1]);
    }

#pragma unroll
    for (int i = 0; i < 2; i++) {
        const int rg = rb + ty2 * 2 + i;
        const float g = gpow[rg + 1];
        const size_t orow = (size_t)(b * L_SEQ + j * CHUNK + rg) * DHEAD;
        O[orow + tx2 * 2 + 0] = o[i][0] + g * cc[i][0];
        O[orow + tx2 * 2 + 1] = o[i][1] + g * cc[i][1];
    }
}

// ---------------------------------------------------------------------------
extern "C" void kernel_launch(void* const* d_in, const int* in_sizes, int n_in,
                              void* d_out, int out_size) {
    const float* X  = (const float*)d_in[0];
    const float* WQ = (const float*)d_in[1];
    const float* WK = (const float*)d_in[2];
    const float* WV = (const float*)d_in[3];
    float* O = (float*)d_out;

    split_kernel<<<4288, 256>>>(X, WQ, WK, WV);
    proj_mma_kernel<<<dim3(ROWS / 64, 3), 256>>>();
    chunk_stats_kernel<<<dim3(NCHUNK, BATCH, 4), 256>>>();
    out_kernel<<<dim3(NCHUNK, BATCH, 2), 512>>>(O);
}

// round 15
// speedup vs baseline: 1.1137x; 1.0568x over previous
#include <cuda_runtime.h>
#include <cuda_bf16.h>
#include <stdint.h>
#include <math.h>

#define L_SEQ 4096
#define BATCH 2
#define HID   1024
#define DHEAD 64
#define CHUNK 64
#define NCHUNK (L_SEQ / CHUNK)
#define ROWS  (BATCH * L_SEQ)
#define GAMMA_F 0.96875f
#define LOG2_GAMMA (-0.04580368961f)
#define SDEPTH 16   // gamma^(64*16) ~ 7e-15: below fp32 noise

// Scratch (__device__ globals; no allocations allowed)
__device__ __nv_bfloat16 g_Xh[ROWS * HID];
__device__ __nv_bfloat16 g_Xl[ROWS * HID];
__device__ __nv_bfloat16 g_Wth[3 * DHEAD * HID];   // [which][n][k]
__device__ __nv_bfloat16 g_Wtl[3 * DHEAD * HID];
__device__ float g_Q[ROWS * DHEAD];
__device__ float g_K[ROWS * DHEAD];
__device__ float g_V[ROWS * DHEAD];
__device__ float g_A[BATCH * NCHUNK * DHEAD * DHEAD];

#define MMA16816(d, a, b)                                                   \
    asm volatile(                                                           \
        "mma.sync.aligned.m16n8k16.row.col.f32.bf16.bf16.f32 "              \
        "{%0,%1,%2,%3}, {%4,%5,%6,%7}, {%8,%9}, {%0,%1,%2,%3};\n"           \
        : "+f"(d[0]), "+f"(d[1]), "+f"(d[2]), "+f"(d[3])                    \
        : "r"(a[0]), "r"(a[1]), "r"(a[2]), "r"(a[3]), "r"(b[0]), "r"(b[1]))

// ---------------------------------------------------------------------------
// P0: split X (fp32 -> bf16 hi/lo) and transpose+split W, one launch.
// ---------------------------------------------------------------------------
__global__ __launch_bounds__(256) void split_kernel(
    const float* __restrict__ X,
    const float* __restrict__ WQ,
    const float* __restrict__ WK,
    const float* __restrict__ WV) {
    if (blockIdx.x < 4096) {
        const size_t tid = (size_t)blockIdx.x * 256 + threadIdx.x;
        const float4* p = (const float4*)X + tid * 2;
        float4 a = p[0], b = p[1];
        float v[8] = {a.x, a.y, a.z, a.w, b.x, b.y, b.z, b.w};
        __nv_bfloat162 hh[4], ll[4];
#pragma unroll
        for (int i = 0; i < 4; i++) {
            __nv_bfloat16 h0 = __float2bfloat16(v[2 * i + 0]);
            __nv_bfloat16 h1 = __float2bfloat16(v[2 * i + 1]);
            hh[i] = __nv_bfloat162(h0, h1);
            ll[i] = __nv_bfloat162(__float2bfloat16(v[2 * i + 0] - __bfloat162float(h0)),
                                   __float2bfloat16(v[2 * i + 1] - __bfloat162float(h1)));
        }
        *(uint4*)&g_Xh[tid * 8] = *(uint4*)hh;
        *(uint4*)&g_Xl[tid * 8] = *(uint4*)ll;
    } else {
        int idx = (blockIdx.x - 4096) * 256 + threadIdx.x;
#pragma unroll
        for (int e = 0; e < 4; e++, idx += 49152) {
            const int which = idx >> 16;
            const int rem   = idx & 65535;
            const int n = rem >> 10, k = rem & 1023;
            const float* W = (which == 0) ? WQ : ((which == 1) ? WK : WV);
            const float v = W[(size_t)k * DHEAD + n];
            __nv_bfloat16 h = __float2bfloat16(v);
            g_Wth[idx] = h;
            g_Wtl[idx] = __float2bfloat16(v - __bfloat162float(h));
        }
    }
}

// ---------------------------------------------------------------------------
// P1: projection (unchanged — near mma.sync roofline).
// ---------------------------------------------------------------------------
__global__ __launch_bounds__(256) void proj_mma_kernel() {
    const int which = blockIdx.y;
    float* __restrict__ Out = (which == 0) ? g_Q : ((which == 1) ? g_K : g_V);
    const __nv_bfloat16* __restrict__ Wh = g_Wth + (size_t)which * DHEAD * HID;
    const __nv_bfloat16* __restrict__ Wl = g_Wtl + (size_t)which * DHEAD * HID;

    __shared__ __nv_bfloat16 Ah[64][72];
    __shared__ __nv_bfloat16 Al[64][72];
    __shared__ __nv_bfloat16 Bh[64][72];
    __shared__ __nv_bfloat16 Bl[64][72];

    const int t    = threadIdx.x;
    const int warp = t >> 5, lane = t & 31;
    const int grp  = lane >> 2, tig = lane & 3;
    const int wm   = warp >> 1;
    const int wn   = warp & 1;
    const int m0   = blockIdx.x * 64;

    const int r0 = t >> 3, c8 = (t & 7) * 8;

    uint4 rXh[2], rXl[2], rWh[2], rWl[2];

    auto issue = [&](int k0) {
#pragma unroll
        for (int e = 0; e < 2; e++) {
            const int row = r0 + e * 32;
            const size_t xo = (size_t)(m0 + row) * HID + k0 + c8;
            rXh[e] = *(const uint4*)(g_Xh + xo);
            rXl[e] = *(const uint4*)(g_Xl + xo);
            const size_t wo = (size_t)row * HID + k0 + c8;
            rWh[e] = *(const uint4*)(Wh + wo);
            rWl[e] = *(const uint4*)(Wl + wo);
        }
    };

    float acc[4][4];
#pragma unroll
    for (int nt = 0; nt < 4; nt++)
#pragma unroll
        for (int c = 0; c < 4; c++) acc[nt][c] = 0.0f;

    issue(0);
    for (int k0 = 0; k0 < HID; k0 += 64) {
#pragma unroll
        for (int e = 0; e < 2; e++) {
            const int row = r0 + e * 32;
            *(uint4*)&Ah[row][c8] = rXh[e];
            *(uint4*)&Al[row][c8] = rXl[e];
            *(uint4*)&Bh[row][c8] = rWh[e];
            *(uint4*)&Bl[row][c8] = rWl[e];
        }
        __syncthreads();
        if (k0 + 64 < HID) issue(k0 + 64);

#pragma unroll
        for (int ks = 0; ks < 64; ks += 16) {
            const int r = wm * 16 + grp;
            const int c = ks + tig * 2;
            uint32_t ah[4], al[4];
            ah[0] = *(const uint32_t*)&Ah[r][c];
            ah[1] = *(const uint32_t*)&Ah[r + 8][c];
            ah[2] = *(const uint32_t*)&Ah[r][c + 8];
            ah[3] = *(const uint32_t*)&Ah[r + 8][c + 8];
            al[0] = *(const uint32_t*)&Al[r][c];
            al[1] = *(const uint32_t*)&Al[r + 8][c];
            al[2] = *(const uint32_t*)&Al[r][c + 8];
            al[3] = *(const uint32_t*)&Al[r + 8][c + 8];
#pragma unroll
            for (int nt = 0; nt < 4; nt++) {
                const int n = wn * 32 + nt * 8 + grp;
                uint32_t bh[2], bl[2];
                bh[0] = *(const uint32_t*)&Bh[n][c];
                bh[1] = *(const uint32_t*)&Bh[n][c + 8];
                bl[0] = *(const uint32_t*)&Bl[n][c];
                bl[1] = *(const uint32_t*)&Bl[n][c + 8];
                MMA16816(acc[nt], ah, bh);
                MMA16816(acc[nt], ah, bl);
                MMA16816(acc[nt], al, bh);
            }
        }
        __syncthreads();
    }

    const bool dox  = (which < 2);
    const bool down = (which == 1);
#pragma unroll
    for (int nt = 0; nt < 4; nt++) {
        const int col = wn * 32 + nt * 8 + tig * 2;
        const int h   = col >> 1;
        float lsv = 0.f, invf = 0.f;
        if (dox) {
            lsv  = __log2f(((float)col + 25.6f) / 89.6f);
            invf = exp2f((float)h * (-13.287712379549449f / 32.0f));
        }
#pragma unroll
        for (int half = 0; half < 2; half++) {
            const int rr = m0 + wm * 16 + grp + half * 8;
            float x0 = acc[nt][half * 2 + 0];
            float x1 = acc[nt][half * 2 + 1];
            if (dox) {
                const float pos = (float)(rr & (L_SEQ - 1));
                float e = lsv * pos * (1.0f / 512.0f);
                if (down) e = -e;
                const float sc = exp2f(e);
                float s, cg;
                sincosf(pos * invf, &s, &cg);
                s *= sc; cg *= sc;
                const float y0 = x0 * cg - x1 * s;
                const float y1 = x1 * cg + x0 * s;
                x0 = y0; x1 = y1;
            }
            *(float2*)(Out + (size_t)rr * DHEAD + col) = make_float2(x0, x1);
        }
    }
}

// ---------------------------------------------------------------------------
// P2: per-chunk decayed A_j = (decayed K)^T V, z-split over 4 column quarters.
// ---------------------------------------------------------------------------
__global__ __launch_bounds__(256) void chunk_stats_kernel() {
    const int j  = blockIdx.x;
    const int b  = blockIdx.y;
    const int cb = blockIdx.z * 16;
    __shared__ float Ks[CHUNK][DHEAD];
    __shared__ float Vs[CHUNK][17];

    const int t = threadIdx.x;
    const size_t base = (size_t)(b * L_SEQ + j * CHUNK) * DHEAD;
    for (int i = t; i < CHUNK * DHEAD; i += 256) {
        const int r = i >> 6, d = i & 63;
        const float w = exp2f((float)(CHUNK - 1 - r) * LOG2_GAMMA);
        Ks[r][d] = g_K[base + i] * w;
    }
    for (int i = t; i < CHUNK * 16; i += 256) {
        const int r = i >> 4, d = i & 15;
        Vs[r][d] = g_V[base + r * DHEAD + cb + d];
    }
    __syncthreads();

    const int ty = t >> 4, tx = t & 15;
    float acc[4] = {0.f, 0.f, 0.f, 0.f};

    for (int r = 0; r < CHUNK; r++) {
        const float v = Vs[r][tx];
#pragma unroll
        for (int i = 0; i < 4; i++)
            acc[i] = fmaf(Ks[r][ty * 4 + i], v, acc[i]);
    }

    float* __restrict__ Ap = g_A + (size_t)(b * NCHUNK + j) * DHEAD * DHEAD;
#pragma unroll
    for (int i = 0; i < 4; i++)
        Ap[(ty * 4 + i) * DHEAD + cb + tx] = acc[i];
}

// ---------------------------------------------------------------------------
// P3: per-chunk output on TENSOR CORES.  Row-split z=2, 256 threads (8 warps).
// P = QK^T (masked), O = P@V + diag(g^(r+1)) Q@S, all via 3-pass bf16 mma.
// smem pitch 72 bf16 -> conflict-free fragment loads (proven in proj).
// ---------------------------------------------------------------------------
struct OutSmem {
    __nv_bfloat16 Qh[32][72], Ql[32][72];   // Q rows rb..rb+31      [m][k]
    __nv_bfloat16 Kh[64][72], Kl[64][72];   // K rows (B for P)      [n][k]
    __nv_bfloat16 Vh[64][72], Vl[64][72];   // V^T (B for O1)        [n=d][k=r']
    __nv_bfloat16 Sh[64][72], Sl[64][72];   // S^T (B for O2)        [n=dout][k=d1]
    __nv_bfloat16 Ph[32][72], Pl[32][72];   // masked P (A for O1)   [m][k=r']
};

__global__ __launch_bounds__(256) void out_mma_kernel(float* __restrict__ O) {
    extern __shared__ char smem_raw[];
    OutSmem* sm = (OutSmem*)smem_raw;

    const int j  = blockIdx.x;
    const int b  = blockIdx.y;
    const int rb = blockIdx.z * 32;          // row base within chunk

    const int t    = threadIdx.x;
    const int warp = t >> 5, lane = t & 31;
    const int grp  = lane >> 2, tig = lane & 3;
    const int wm   = warp >> 2;              // 0..1 -> 16-row tile
    const int wn2  = (warp & 3) * 2;         // n-tile base (2 tiles of 8 cols)

    const size_t cbase = (size_t)(b * L_SEQ + j * CHUNK) * DHEAD;

    // ---- fills ----
    {   // Q rows rb..rb+31: 8 elems/thread
        const int r = t >> 3, d0 = (t & 7) * 8;
        float4 u0 = *(const float4*)(g_Q + cbase + (rb + r) * DHEAD + d0);
        float4 u1 = *(const float4*)(g_Q + cbase + (rb + r) * DHEAD + d0 + 4);
        float v[8] = {u0.x, u0.y, u0.z, u0.w, u1.x, u1.y, u1.z, u1.w};
#pragma unroll
        for (int e = 0; e < 8; e++) {
            __nv_bfloat16 h = __float2bfloat16(v[e]);
            sm->Qh[r][d0 + e] = h;
            sm->Ql[r][d0 + e] = __float2bfloat16(v[e] - __bfloat162float(h));
        }
    }
    {   // K (natural) and V (transposed): 16 elems/thread each
        const int r = t >> 2, d0 = (t & 3) * 16;
#pragma unroll
        for (int q4 = 0; q4 < 4; q4++) {
            float4 u = *(const float4*)(g_K + cbase + r * DHEAD + d0 + q4 * 4);
            float v[4] = {u.x, u.y, u.z, u.w};
#pragma unroll
            for (int e = 0; e < 4; e++) {
                __nv_bfloat16 h = __float2bfloat16(v[e]);
                sm->Kh[r][d0 + q4 * 4 + e] = h;
                sm->Kl[r][d0 + q4 * 4 + e] = __float2bfloat16(v[e] - __bfloat162float(h));
            }
        }
#pragma unroll
        for (int q4 = 0; q4 < 4; q4++) {
            float4 u = *(const float4*)(g_V + cbase + r * DHEAD + d0 + q4 * 4);
            float v[4] = {u.x, u.y, u.z, u.w};
#pragma unroll
            for (int e = 0; e < 4; e++) {
                __nv_bfloat16 h = __float2bfloat16(v[e]);
                sm->Vh[d0 + q4 * 4 + e][r] = h;      // transposed
                sm->Vl[d0 + q4 * 4 + e][r] = __float2bfloat16(v[e] - __bfloat162float(h));
            }
        }
    }
    {   // windowed state S_j (fp32 accum in regs) -> transposed bf16 split
        const int sr = t >> 2, d0 = (t & 3) * 16;
        float s16[16];
#pragma unroll
        for (int e = 0; e < 16; e++) s16[e] = 0.0f;
        const int dmax = (j < SDEPTH) ? j : SDEPTH;
        const float gC = exp2f((float)CHUNK * LOG2_GAMMA);
        float w = 1.0f;
        for (int d = 1; d <= dmax; d++) {
            const float* Ap = g_A + (size_t)(b * NCHUNK + j - d) * 4096 + sr * DHEAD + d0;
#pragma unroll
            for (int q4 = 0; q4 < 4; q4++) {
                float4 u = *(const float4*)(Ap + q4 * 4);
                s16[q4 * 4 + 0] += w * u.x; s16[q4 * 4 + 1] += w * u.y;
                s16[q4 * 4 + 2] += w * u.z; s16[q4 * 4 + 3] += w * u.w;
            }
            w *= gC;
        }
#pragma unroll
        for (int e = 0; e < 16; e++) {
            __nv_bfloat16 h = __float2bfloat16(s16[e]);
            sm->Sh[d0 + e][sr] = h;                   // transposed
            sm->Sl[d0 + e][sr] = __float2bfloat16(s16[e] - __bfloat162float(h));
        }
    }
    __syncthreads();

    // ---- shared 3-pass gemm helper: acc[2][4] += A[32xk64] * B[n64xk64]^T ----
    auto gemm3 = [&](const __nv_bfloat16 (*Ah_)[72], const __nv_bfloat16 (*Al_)[72],
                     const __nv_bfloat16 (*Bh_)[72], const __nv_bfloat16 (*Bl_)[72],
                     float acc[2][4]) {
#pragma unroll
        for (int pass = 0; pass < 3; pass++) {
            const __nv_bfloat16 (*Ap)[72] = (pass == 2) ? Al_ : Ah_;
            const __nv_bfloat16 (*Bp)[72] = (pass == 1) ? Bl_ : Bh_;
#pragma unroll
            for (int k0 = 0; k0 < 64; k0 += 16) {
                const int c = k0 + tig * 2;
                const int r = wm * 16 + grp;
                uint32_t a[4];
                a[0] = *(const uint32_t*)&Ap[r][c];
                a[1] = *(const uint32_t*)&Ap[r + 8][c];
                a[2] = *(const uint32_t*)&Ap[r][c + 8];
                a[3] = *(const uint32_t*)&Ap[r + 8][c + 8];
#pragma unroll
                for (int nt = 0; nt < 2; nt++) {
                    const int n = (wn2 + nt) * 8 + grp;
                    uint32_t bb[2];
                    bb[0] = *(const uint32_t*)&Bp[n][c];
                    bb[1] = *(const uint32_t*)&Bp[n][c + 8];
                    MMA16816(acc[nt], a, bb);
                }
            }
        }
    };

    // ---- P = Q K^T, mask+decay in regs, split to smem ----
    {
        float pc[2][4];
#pragma unroll
        for (int nt = 0; nt < 2; nt++)
#pragma unroll
            for (int e = 0; e < 4; e++) pc[nt][e] = 0.0f;
        gemm3(sm->Qh, sm->Ql, sm->Kh, sm->Kl, pc);

#pragma unroll
        for (int nt = 0; nt < 2; nt++) {
#pragma unroll
            for (int e = 0; e < 4; e++) {
                const int rl = wm * 16 + grp + 8 * (e >> 1);      // local row
                const int rg = rb + rl;                           // global row in chunk
                const int rp = (wn2 + nt) * 8 + tig * 2 + (e & 1);
                const int m  = rg - rp;
                const float f = (m >= 0) ? exp2f((float)m * LOG2_GAMMA) : 0.0f;
                const float pv = pc[nt][e] * f;
                __nv_bfloat16 h = __float2bfloat16(pv);
                sm->Ph[rl][rp] = h;
                sm->Pl[rl][rp] = __float2bfloat16(pv - __bfloat162float(h));
            }
        }
    }
    __syncthreads();

    // ---- O1 = P @ V^T-layout,  O2 = Q @ S^T-layout ----
    float oc[2][4], qc[2][4];
#pragma unroll
    for (int nt = 0; nt < 2; nt++)
#pragma unroll
        for (int e = 0; e < 4; e++) { oc[nt][e] = 0.0f; qc[nt][e] = 0.0f; }
    gemm3(sm->Ph, sm->Pl, sm->Vh, sm->Vl, oc);
    gemm3(sm->Qh, sm->Ql, sm->Sh, sm->Sl, qc);

    // ---- epilogue: O = O1 + g^(rg+1) * O2 ----
#pragma unroll
    for (int nt = 0; nt < 2; nt++) {
        const int col = (wn2 + nt) * 8 + tig * 2;
#pragma unroll
        for (int half = 0; half < 2; half++) {
            const int rg = rb + wm * 16 + grp + 8 * half;
            const float g = exp2f((float)(rg + 1) * LOG2_GAMMA);
            const size_t orow = cbase + (size_t)rg * DHEAD;
            float2 val;
            val.x = oc[nt][half * 2 + 0] + g * qc[nt][half * 2 + 0];
            val.y = oc[nt][half * 2 + 1] + g * qc[nt][half * 2 + 1];
            *(float2*)(O + orow + col) = val;
        }
    }
}

// ---------------------------------------------------------------------------
extern "C" void kernel_launch(void* const* d_in, const int* in_sizes, int n_in,
                              void* d_out, int out_size) {
    const float* X  = (const float*)d_in[0];
    const float* WQ = (const float*)d_in[1];
    const float* WK = (const float*)d_in[2];
    const float* WV = (const float*)d_in[3];
    float* O = (float*)d_out;

    cudaFuncSetAttribute(out_mma_kernel,
                         cudaFuncAttributeMaxDynamicSharedMemorySize,
                         (int)sizeof(OutSmem));

    split_kernel<<<4288, 256>>>(X, WQ, WK, WV);
    proj_mma_kernel<<<dim3(ROWS / 64, 3), 256>>>();
    chunk_stats_kernel<<<dim3(NCHUNK, BATCH, 4), 256>>>();
    out_mma_kernel<<<dim3(NCHUNK, BATCH, 2), 256, sizeof(OutSmem)>>>(O);
}